// round 7
// baseline (speedup 1.0000x reference)
#include <cuda_runtime.h>
#include <cuda_fp16.h>
#include <cstdint>

#define BB 256
#define NN 2048
#define DD 128
#define RPB 2048
#define TILE_R 64
#define TILES (BB*32)             // 8192 tiles
#define GRID_MAIN 296             // 2 persistent CTAs/SM
// smem: W16 [0,32768) | E16 x2 [32768,65536) | D [65536,99328) | segs x2 [99328,99840)
#define SMEM_MAIN 99840

// ---------------- device scratch ----------------
__device__ float g_acc[BB*DD];
__device__ int   g_hist[BB*BB];
__device__ int   g_perm[BB*RPB];   // packed: (node_idx<<8)|seg ; sentinel has sign bit
__device__ float g_T[BB*DD];

// ---------------- helpers ----------------
static __device__ __forceinline__ uint32_t smem_u32(const void* p){
  uint32_t a;
  asm("{ .reg .u64 t; cvta.to.shared.u64 t, %1; cvt.u32.u64 %0, t; }" : "=r"(a) : "l"(p));
  return a;
}
static __device__ __forceinline__ uint32_t h2u(__half2 h){
  union { __half2 h; uint32_t u; } c; c.h = h; return c.u;
}
static __device__ __forceinline__ void ldsm4(uint32_t &r0, uint32_t &r1, uint32_t &r2, uint32_t &r3, uint32_t a){
  asm volatile("ldmatrix.sync.aligned.m8n8.x4.shared.b16 {%0,%1,%2,%3}, [%4];"
    : "=r"(r0), "=r"(r1), "=r"(r2), "=r"(r3) : "r"(a));
}
static __device__ __forceinline__ void mma16816(float* c, uint32_t a0, uint32_t a1, uint32_t a2, uint32_t a3,
                                                uint32_t b0, uint32_t b1){
  asm volatile("mma.sync.aligned.m16n8k16.row.col.f32.f16.f16.f32 "
    "{%0,%1,%2,%3}, {%4,%5,%6,%7}, {%8,%9}, {%0,%1,%2,%3};"
    : "+f"(c[0]), "+f"(c[1]), "+f"(c[2]), "+f"(c[3])
    : "r"(a0), "r"(a1), "r"(a2), "r"(a3), "r"(b0), "r"(b1));
}

// ---------------- fused prep ----------------
__global__ void __launch_bounds__(512) k_prep(const int* __restrict__ bidx,
                                              const float* __restrict__ embs,
                                              const float* __restrict__ W1,
                                              const float* __restrict__ b1){
  int b = blockIdx.x, t = threadIdx.x;
  if (b < BB){
    __shared__ int h[BB];
    __shared__ int wsum[8];
    if (t < BB) h[t] = 0;
    if (t < DD) g_acc[b*DD + t] = 0.f;
    __syncthreads();
    for (int i = t; i < NN-1; i += 512)
      atomicAdd(&h[bidx[b*NN + 1 + i]], 1);
    __syncthreads();
    int lane = t & 31, wrp = t >> 5;
    int v = 0, x = 0;
    if (t < BB){ v = h[t]; g_hist[b*BB + t] = v; }
    x = v;
    #pragma unroll
    for (int o = 1; o < 32; o <<= 1){
      int y = __shfl_up_sync(0xffffffffu, x, o);
      if (lane >= o) x += y;
    }
    if (t < BB && lane == 31) wsum[wrp] = x;
    __syncthreads();
    if (t < 32){
      int s = (t < 8) ? wsum[t] : 0;
      #pragma unroll
      for (int o = 1; o < 8; o <<= 1){
        int y = __shfl_up_sync(0xffffffffu, s, o);
        if (t >= o) s += y;
      }
      if (t < 8) wsum[t] = s;
    }
    __syncthreads();
    if (t < BB){
      int off = (wrp > 0) ? wsum[wrp-1] : 0;
      h[t] = off + x - v;
    }
    __syncthreads();
    for (int i = t; i < NN-1; i += 512){
      int s = bidx[b*NN + 1 + i];
      int pos = atomicAdd(&h[s], 1);
      g_perm[b*RPB + pos] = ((1 + i) << 8) | s;     // packed
    }
    if (t == 0) g_perm[b*RPB + NN-1] = (int)(0x80000000u | (1u << 8));  // sentinel: node 1, skip
  } else {
    int bb = b - BB;
    __shared__ float tg[DD];
    if (t < DD) tg[t] = embs[(size_t)bb*NN*DD + t];
    __syncthreads();
    if (t < DD){
      float s = b1[t];
      const float* w = W1 + (size_t)t*2*DD;
      #pragma unroll 8
      for (int k = 0; k < DD; k++) s += w[k]*tg[k];
      g_T[bb*DD + t] = s;
    }
  }
}

// ---------------- main persistent HMMA kernel: 256 thr, double-buffered E ----------------
__global__ void __launch_bounds__(256, 2) k_main(const float* __restrict__ embs,
                                                 const float* __restrict__ W1){
  extern __shared__ char sm[];
  float* Dm = (float*)(sm + 65536);
  int* segs = (int*)(sm + 99328);       // 2 x 64 ints
  uint32_t sbase = smem_u32(sm);
  const uint32_t Wb = sbase;
  const uint32_t Ebuf[2] = { sbase + 32768, sbase + 49152 };

  int tid = threadIdx.x;
  int lane = tid & 31, w = tid >> 5;

  // ---- convert W1b -> smem fp16 once (thread = (row d, half)) ----
  {
    int d = tid >> 1, hh = tid & 1;
    const float4* wr = (const float4*)(W1 + (size_t)d*2*DD + DD + hh*64);
    uint32_t sw = (uint32_t)(d & 7) << 4;
    char* dst = sm + d*256;
    #pragma unroll
    for (int i = 0; i < 8; i++){
      float4 v0 = wr[2*i], v1 = wr[2*i+1];
      uint4 q;
      q.x = h2u(__floats2half2_rn(v0.x, v0.y));
      q.y = h2u(__floats2half2_rn(v0.z, v0.w));
      q.z = h2u(__floats2half2_rn(v1.x, v1.y));
      q.w = h2u(__floats2half2_rn(v1.z, v1.w));
      *(uint4*)(dst + (((uint32_t)(hh*128 + i*16)) ^ sw)) = q;
    }
  }

  // warp tile: rows (w&3)*16, cols (w>>2)*64
  const int wr16 = (w & 3) * 16;
  const int wc64 = (w >> 2) * 64;
  const uint32_t ln15 = lane & 15;
  const uint32_t sxor = (uint32_t)(lane & 7) << 4;
  const uint32_t kbl  = (uint32_t)(lane >> 4) << 4;
  const uint32_t baseB = Wb + (uint32_t)(wc64 + ln15)*256;

  // gather mapping: thread -> (row er = tid>>2, quarter q = tid&3) : 32 floats
  const int er = tid >> 2, eq = tid & 3;
  const uint32_t esw = (uint32_t)(er & 7) << 4;

  // ---- prologue: fill E[0] + segs[0] ----
  int tile = blockIdx.x;
  {
    int rowbase = (tile >> 5)*RPB + (tile & 31)*TILE_R;
    int pv = g_perm[rowbase + er];
    if (eq == 0) segs[er] = pv;
    int node = (pv >> 8) & 2047;
    const float4* src = (const float4*)(embs + ((size_t)(tile >> 5)*NN + node)*DD + eq*32);
    char* edst = (char*)sm + 32768 + er*256;
    #pragma unroll
    for (int i = 0; i < 4; i++){
      float4 v0 = src[2*i], v1 = src[2*i+1];
      uint4 qq;
      qq.x = h2u(__floats2half2_rn(v0.x, v0.y));
      qq.y = h2u(__floats2half2_rn(v0.z, v0.w));
      qq.z = h2u(__floats2half2_rn(v1.x, v1.y));
      qq.w = h2u(__floats2half2_rn(v1.z, v1.w));
      *(uint4*)(edst + (((uint32_t)(eq*64 + i*16)) ^ esw)) = qq;
    }
    __syncthreads();
  }

  int buf = 0;
  for (; tile < TILES; tile += GRID_MAIN, buf ^= 1){
    int nxt = tile + GRID_MAIN;
    // ---- issue prefetch LDGs for next tile (latency covered by MMA) ----
    float4 pf[8];
    int pv_n = 0;
    if (nxt < TILES){
      int nrowbase = (nxt >> 5)*RPB + (nxt & 31)*TILE_R;
      pv_n = g_perm[nrowbase + er];
      int node = (pv_n >> 8) & 2047;
      const float4* src = (const float4*)(embs + ((size_t)(nxt >> 5)*NN + node)*DD + eq*32);
      #pragma unroll
      for (int i = 0; i < 8; i++) pf[i] = src[i];
    }

    // ---- MMA: warp computes D[wr16..+15][wc64..+63], K=128 ----
    const uint32_t baseA = Ebuf[buf] + (uint32_t)(wr16 + ln15)*256;
    float acc[8][4];
    #pragma unroll
    for (int i = 0; i < 8; i++){ acc[i][0]=0.f; acc[i][1]=0.f; acc[i][2]=0.f; acc[i][3]=0.f; }
    #pragma unroll
    for (int k0 = 0; k0 < 8; k0++){
      uint32_t ko = (((uint32_t)k0 << 5) | kbl) ^ sxor;
      uint32_t a0, a1, a2, a3;
      ldsm4(a0, a1, a2, a3, baseA + ko);
      uint32_t bad = baseB + ko;
      #pragma unroll
      for (int j = 0; j < 4; j++){
        uint32_t b0, b1, b2, b3;
        ldsm4(b0, b1, b2, b3, bad);
        bad += 16*256;
        mma16816(acc[2*j],   a0, a1, a2, a3, b0, b2);
        mma16816(acc[2*j+1], a0, a1, a2, a3, b1, b3);
      }
    }

    // ---- D store (pad-132) ----
    {
      int r0 = wr16 + (lane >> 2);
      int c0 = wc64 + 2*(lane & 3);
      #pragma unroll
      for (int nt = 0; nt < 8; nt++){
        *(float2*)(Dm + r0*132 + c0 + nt*8)     = make_float2(acc[nt][0], acc[nt][1]);
        *(float2*)(Dm + (r0+8)*132 + c0 + nt*8) = make_float2(acc[nt][2], acc[nt][3]);
      }
    }

    // ---- convert + store next E into other buffer ----
    if (nxt < TILES){
      char* edst = (char*)sm + 32768 + (buf^1)*16384 + er*256;
      if (eq == 0) segs[(buf^1)*64 + er] = pv_n;
      #pragma unroll
      for (int i = 0; i < 4; i++){
        uint4 qq;
        qq.x = h2u(__floats2half2_rn(pf[2*i].x, pf[2*i].y));
        qq.y = h2u(__floats2half2_rn(pf[2*i].z, pf[2*i].w));
        qq.z = h2u(__floats2half2_rn(pf[2*i+1].x, pf[2*i+1].y));
        qq.w = h2u(__floats2half2_rn(pf[2*i+1].z, pf[2*i+1].w));
        *(uint4*)(edst + (((uint32_t)(eq*64 + i*16)) ^ esw)) = qq;
      }
    }
    __syncthreads();

    // ---- epilogue: thread = (d = tid&127, rowhalf = tid>>7) ----
    {
      int d = tid & 127;
      int rbeg = (tid >> 7) * 32;
      float t_d = g_T[(tile >> 5)*DD + d];
      int cur = -1; float run = 0.f;
      #pragma unroll 8
      for (int r = rbeg; r < rbeg + 32; r++){
        int pv = segs[buf*64 + r];
        int s = (pv < 0) ? -1 : (pv & 255);
        float v = fmaxf(Dm[r*132 + d] + t_d, 0.f);
        if (s != cur){
          if (cur >= 0) atomicAdd(&g_acc[cur*DD + d], run);
          run = 0.f; cur = s;
        }
        if (s >= 0) run += v;
      }
      if (cur >= 0) atomicAdd(&g_acc[cur*DD + d], run);
    }
    __syncthreads();
  }
}

// ---------------- final: out[s] = W2 . acc[s] + b2 * count_s ----------------
__global__ void __launch_bounds__(128) k_final(const float* __restrict__ W2,
                                               const float* __restrict__ b2,
                                               float* __restrict__ out){
  __shared__ float arow[DD];
  __shared__ int red[DD];
  int s = blockIdx.x, d = threadIdx.x;
  arow[d] = g_acc[s*DD + d];
  red[d] = g_hist[d*BB + s] + g_hist[(d + 128)*BB + s];
  __syncthreads();
  #pragma unroll
  for (int o = 64; o > 0; o >>= 1){
    if (d < o) red[d] += red[d + o];
    __syncthreads();
  }
  float r = 0.f;
  const float* ww = W2 + (size_t)d*DD;
  #pragma unroll 8
  for (int j = 0; j < DD; j++) r += ww[j]*arow[j];
  out[s*DD + d] = r + b2[d]*(float)red[0];
}

// ---------------- launch ----------------
extern "C" void kernel_launch(void* const* d_in, const int* in_sizes, int n_in,
                              void* d_out, int out_size){
  const float* embs = (const float*)d_in[0];
  const float* W1   = (const float*)d_in[1];
  const float* b1   = (const float*)d_in[2];
  const float* W2   = (const float*)d_in[3];
  const float* b2   = (const float*)d_in[4];
  const int*   bidx = (const int*)d_in[5];
  float* out = (float*)d_out;

  cudaFuncSetAttribute(k_main, cudaFuncAttributeMaxDynamicSharedMemorySize, SMEM_MAIN);

  k_prep <<<2*BB, 512>>>(bidx, embs, W1, b1);
  k_main <<<GRID_MAIN, 256, SMEM_MAIN>>>(embs, W1);
  k_final<<<BB, DD>>>(W2, b2, out);
}

// round 8
// speedup vs baseline: 1.1701x; 1.1701x over previous
#include <cuda_runtime.h>
#include <cuda_fp16.h>
#include <cstdint>

#define BB 256
#define NN 2048
#define DD 128
#define RPB 2048
#define SLICES (BB*128)           // 32768 16-row slices
#define GRID_MAIN 296             // 2 persistent CTAs/SM
#define WSTRIDE (GRID_MAIN*8)     // warp-slice stride
// smem: W16 [0,32768) | E per-warp 8x4096 [32768,65536) | D per-warp 8x4224 [65536,99328)
#define SMEM_MAIN 99328

// ---------------- device scratch ----------------
__device__ float g_acc[BB*DD];
__device__ int   g_histT[BB*BB];   // [seg][batch]
__device__ int   g_perm[BB*RPB];   // packed (node<<8)|seg ; sentinel sign bit
__device__ float g_T[BB*DD];

// ---------------- helpers ----------------
static __device__ __forceinline__ uint32_t smem_u32(const void* p){
  uint32_t a;
  asm("{ .reg .u64 t; cvta.to.shared.u64 t, %1; cvt.u32.u64 %0, t; }" : "=r"(a) : "l"(p));
  return a;
}
static __device__ __forceinline__ uint32_t h2u(__half2 h){
  union { __half2 h; uint32_t u; } c; c.h = h; return c.u;
}
static __device__ __forceinline__ void ldsm4(uint32_t &r0, uint32_t &r1, uint32_t &r2, uint32_t &r3, uint32_t a){
  asm volatile("ldmatrix.sync.aligned.m8n8.x4.shared.b16 {%0,%1,%2,%3}, [%4];"
    : "=r"(r0), "=r"(r1), "=r"(r2), "=r"(r3) : "r"(a));
}
static __device__ __forceinline__ void mma16816(float* c, uint32_t a0, uint32_t a1, uint32_t a2, uint32_t a3,
                                                uint32_t b0, uint32_t b1){
  asm volatile("mma.sync.aligned.m16n8k16.row.col.f32.f16.f16.f32 "
    "{%0,%1,%2,%3}, {%4,%5,%6,%7}, {%8,%9}, {%0,%1,%2,%3};"
    : "+f"(c[0]), "+f"(c[1]), "+f"(c[2]), "+f"(c[3])
    : "r"(a0), "r"(a1), "r"(a2), "r"(a3), "r"(b0), "r"(b1));
}

// ---------------- fused prep ----------------
__global__ void __launch_bounds__(512) k_prep(const int* __restrict__ bidx,
                                              const float* __restrict__ embs,
                                              const float* __restrict__ W1,
                                              const float* __restrict__ b1){
  int b = blockIdx.x, t = threadIdx.x;
  if (b < BB){
    __shared__ int h[BB];
    __shared__ int wsum[8];
    if (t < BB) h[t] = 0;
    if (t < DD) g_acc[b*DD + t] = 0.f;
    __syncthreads();
    for (int i = t; i < NN-1; i += 512)
      atomicAdd(&h[bidx[b*NN + 1 + i]], 1);
    __syncthreads();
    int lane = t & 31, wrp = t >> 5;
    int v = 0, x = 0;
    if (t < BB){ v = h[t]; g_histT[t*BB + b] = v; }
    x = v;
    #pragma unroll
    for (int o = 1; o < 32; o <<= 1){
      int y = __shfl_up_sync(0xffffffffu, x, o);
      if (lane >= o) x += y;
    }
    if (t < BB && lane == 31) wsum[wrp] = x;
    __syncthreads();
    if (t < 32){
      int s = (t < 8) ? wsum[t] : 0;
      #pragma unroll
      for (int o = 1; o < 8; o <<= 1){
        int y = __shfl_up_sync(0xffffffffu, s, o);
        if (t >= o) s += y;
      }
      if (t < 8) wsum[t] = s;
    }
    __syncthreads();
    if (t < BB){
      int off = (wrp > 0) ? wsum[wrp-1] : 0;
      h[t] = off + x - v;
    }
    __syncthreads();
    for (int i = t; i < NN-1; i += 512){
      int s = bidx[b*NN + 1 + i];
      int pos = atomicAdd(&h[s], 1);
      g_perm[b*RPB + pos] = ((1 + i) << 8) | s;
    }
    if (t == 0) g_perm[b*RPB + NN-1] = (int)(0x80000000u | (1u << 8));
  } else {
    // prepT: d = t>>2, k-quarter = t&3 (32 k each), shuffle-combine
    int bb = b - BB;
    __shared__ float tg[DD];
    if (t < DD) tg[t] = embs[(size_t)bb*NN*DD + t];
    __syncthreads();
    int d = t >> 2, kq = t & 3;
    const float* w = W1 + (size_t)d*2*DD + kq*32;
    const float* tgp = tg + kq*32;
    float s = 0.f;
    #pragma unroll
    for (int k = 0; k < 32; k++) s += w[k]*tgp[k];
    s += __shfl_xor_sync(0xffffffffu, s, 1);
    s += __shfl_xor_sync(0xffffffffu, s, 2);
    if (kq == 0) g_T[bb*DD + d] = s + b1[d];
  }
}

// ---------------- main: warp-autonomous 16-row slices, no block barriers ----------------
__global__ void __launch_bounds__(256, 2) k_main(const float* __restrict__ embs,
                                                 const float* __restrict__ W1,
                                                 int slice_lo, int slice_hi){
  extern __shared__ char sm[];
  uint32_t sbase = smem_u32(sm);
  const uint32_t Wb = sbase;

  int tid = threadIdx.x;
  int lane = tid & 31, w = tid >> 5;

  const uint32_t Eb = sbase + 32768 + (uint32_t)w*4096;
  float* Dw = (float*)(sm + 65536 + w*4224);

  // ---- W1b -> smem fp16 once ----
  {
    int d = tid >> 1, hh = tid & 1;
    const float4* wr = (const float4*)(W1 + (size_t)d*2*DD + DD + hh*64);
    uint32_t sw = (uint32_t)(d & 7) << 4;
    char* dst = sm + d*256;
    #pragma unroll
    for (int i = 0; i < 8; i++){
      float4 v0 = wr[2*i], v1 = wr[2*i+1];
      uint4 q;
      q.x = h2u(__floats2half2_rn(v0.x, v0.y));
      q.y = h2u(__floats2half2_rn(v0.z, v0.w));
      q.z = h2u(__floats2half2_rn(v1.x, v1.y));
      q.w = h2u(__floats2half2_rn(v1.z, v1.w));
      *(uint4*)(dst + (((uint32_t)(hh*128 + i*16)) ^ sw)) = q;
    }
  }
  __syncthreads();   // only block barrier

  const uint32_t ln15 = lane & 15;
  const uint32_t sxor = (uint32_t)(lane & 7) << 4;
  const uint32_t kbl  = (uint32_t)(lane >> 4) << 4;
  const uint32_t baseA = Eb + ln15*256;
  const uint32_t baseB = Wb + ln15*256;

  // gather mapping: lane -> (row r2 = lane>>1, half h = lane&1)
  const int r2 = lane >> 1, eh = lane & 1;
  char* edst = (char*)sm + 32768 + w*4096 + r2*256;
  const uint32_t esw = (uint32_t)(r2 & 7) << 4;

  for (int slice = slice_lo + blockIdx.x*8 + w; slice < slice_hi; slice += WSTRIDE){
    int batch = slice >> 7;
    int rowbase = batch*RPB + (slice & 127)*16;

    // ---- gather 16 rows -> fp16 swizzled E (warp-private) ----
    int pv = g_perm[rowbase + r2];
    {
      int node = (pv >> 8) & 2047;
      const float4* src = (const float4*)(embs + ((size_t)batch*NN + node)*DD + eh*64);
      #pragma unroll
      for (int half = 0; half < 2; half++){
        float4 vv[8];
        #pragma unroll
        for (int i = 0; i < 8; i++) vv[i] = src[half*8 + i];
        #pragma unroll
        for (int i = 0; i < 4; i++){
          uint4 q;
          q.x = h2u(__floats2half2_rn(vv[2*i].x, vv[2*i].y));
          q.y = h2u(__floats2half2_rn(vv[2*i].z, vv[2*i].w));
          q.z = h2u(__floats2half2_rn(vv[2*i+1].x, vv[2*i+1].y));
          q.w = h2u(__floats2half2_rn(vv[2*i+1].z, vv[2*i+1].w));
          *(uint4*)(edst + (((uint32_t)(eh*128 + half*64 + i*16)) ^ esw)) = q;
        }
      }
    }
    __syncwarp();

    // ---- MMA: 16 rows x 128 cols, K=128 ----
    float acc[16][4];
    #pragma unroll
    for (int i = 0; i < 16; i++){ acc[i][0]=0.f; acc[i][1]=0.f; acc[i][2]=0.f; acc[i][3]=0.f; }
    #pragma unroll
    for (int k0 = 0; k0 < 8; k0++){
      uint32_t ko = (((uint32_t)k0 << 5) | kbl) ^ sxor;
      uint32_t a0, a1, a2, a3;
      ldsm4(a0, a1, a2, a3, baseA + ko);
      uint32_t bad = baseB + ko;
      #pragma unroll
      for (int j = 0; j < 8; j++){
        uint32_t b0, b1, b2, b3;
        ldsm4(b0, b1, b2, b3, bad);
        bad += 16*256;
        mma16816(acc[2*j],   a0, a1, a2, a3, b0, b2);
        mma16816(acc[2*j+1], a0, a1, a2, a3, b1, b3);
      }
    }
    __syncwarp();   // E reads done (E reused next iter)

    // ---- epilogue: two 8-row passes through warp-private D ----
    float tv[4];
    #pragma unroll
    for (int j = 0; j < 4; j++) tv[j] = g_T[batch*DD + lane + 32*j];

    int r0 = lane >> 2;
    int c0 = 2*(lane & 3);
    int cur = -1;
    float run[4] = {0.f, 0.f, 0.f, 0.f};

    // rows 0-7 (acc[.][0..1])
    #pragma unroll
    for (int nt = 0; nt < 16; nt++)
      *(float2*)(Dw + r0*132 + c0 + nt*8) = make_float2(acc[nt][0], acc[nt][1]);
    __syncwarp();
    #pragma unroll
    for (int r = 0; r < 8; r++){
      int pvr = __shfl_sync(0xffffffffu, pv, 2*r);
      int s = (pvr < 0) ? -1 : (pvr & 255);
      if (s != cur){
        if (cur >= 0){
          #pragma unroll
          for (int j = 0; j < 4; j++) atomicAdd(&g_acc[cur*DD + lane + 32*j], run[j]);
        }
        run[0]=run[1]=run[2]=run[3]=0.f;
        cur = s;
      }
      if (s >= 0){
        #pragma unroll
        for (int j = 0; j < 4; j++)
          run[j] += fmaxf(Dw[r*132 + lane + 32*j] + tv[j], 0.f);
      }
    }
    __syncwarp();

    // rows 8-15 (acc[.][2..3])
    #pragma unroll
    for (int nt = 0; nt < 16; nt++)
      *(float2*)(Dw + r0*132 + c0 + nt*8) = make_float2(acc[nt][2], acc[nt][3]);
    __syncwarp();
    #pragma unroll
    for (int r = 0; r < 8; r++){
      int pvr = __shfl_sync(0xffffffffu, pv, 2*(r + 8));
      int s = (pvr < 0) ? -1 : (pvr & 255);
      if (s != cur){
        if (cur >= 0){
          #pragma unroll
          for (int j = 0; j < 4; j++) atomicAdd(&g_acc[cur*DD + lane + 32*j], run[j]);
        }
        run[0]=run[1]=run[2]=run[3]=0.f;
        cur = s;
      }
      if (s >= 0){
        #pragma unroll
        for (int j = 0; j < 4; j++)
          run[j] += fmaxf(Dw[r*132 + lane + 32*j] + tv[j], 0.f);
      }
    }
    if (cur >= 0){
      #pragma unroll
      for (int j = 0; j < 4; j++) atomicAdd(&g_acc[cur*DD + lane + 32*j], run[j]);
    }
    __syncwarp();   // D reads done before next slice overwrites
  }
}

// ---------------- final: out[s] = W2 . acc[s] + b2 * count_s ----------------
__global__ void __launch_bounds__(128) k_final(const float* __restrict__ W2,
                                               const float* __restrict__ b2,
                                               float* __restrict__ out){
  __shared__ float arow[DD];
  __shared__ int red[DD];
  int s = blockIdx.x, d = threadIdx.x;
  arow[d] = g_acc[s*DD + d];
  red[d] = g_histT[s*BB + d] + g_histT[s*BB + d + 128];
  __syncthreads();
  #pragma unroll
  for (int o = 64; o > 0; o >>= 1){
    if (d < o) red[d] += red[d + o];
    __syncthreads();
  }
  float r = 0.f;
  const float* ww = W2 + (size_t)d*DD;
  #pragma unroll 8
  for (int j = 0; j < DD; j++) r += ww[j]*arow[j];
  out[s*DD + d] = r + b2[d]*(float)red[0];
}

// ---------------- launch ----------------
extern "C" void kernel_launch(void* const* d_in, const int* in_sizes, int n_in,
                              void* d_out, int out_size){
  const float* embs = (const float*)d_in[0];
  const float* W1   = (const float*)d_in[1];
  const float* b1   = (const float*)d_in[2];
  const float* W2   = (const float*)d_in[3];
  const float* b2   = (const float*)d_in[4];
  const int*   bidx = (const int*)d_in[5];
  float* out = (float*)d_out;

  cudaFuncSetAttribute(k_main, cudaFuncAttributeMaxDynamicSharedMemorySize, SMEM_MAIN);

  k_prep <<<2*BB, 512>>>(bidx, embs, W1, b1);
  k_main <<<GRID_MAIN, 256, SMEM_MAIN>>>(embs, W1, 0, SLICES/2);        // launch idx 1 (and 5 on replay)
  k_main <<<GRID_MAIN, 256, SMEM_MAIN>>>(embs, W1, SLICES/2, SLICES);   // launch idx 2
  k_final<<<BB, DD>>>(W2, b2, out);
}

// round 9
// speedup vs baseline: 1.2403x; 1.0599x over previous
#include <cuda_runtime.h>
#include <cuda_fp16.h>
#include <cstdint>

#define BB 256
#define NN 2048
#define DD 128
#define RPB 2048
#define SLICES (BB*128)           // 32768 16-row slices
#define GRID_MAIN 296             // 2 persistent CTAs/SM
#define WSTRIDE (GRID_MAIN*8)
// smem: W16 [0,32768) | per-warp E/D overlay 8 x 4224 [32768,66560)
#define SMEM_MAIN 66560

// ---------------- device scratch ----------------
__device__ float g_acc[BB*DD];
__device__ int   g_histT[BB*BB];   // [seg][batch]
__device__ int   g_perm[BB*RPB];   // packed (node<<8)|seg ; sentinel sign bit
__device__ float g_T[BB*DD];

// ---------------- helpers ----------------
static __device__ __forceinline__ uint32_t smem_u32(const void* p){
  uint32_t a;
  asm("{ .reg .u64 t; cvta.to.shared.u64 t, %1; cvt.u32.u64 %0, t; }" : "=r"(a) : "l"(p));
  return a;
}
static __device__ __forceinline__ uint32_t h2u(__half2 h){
  union { __half2 h; uint32_t u; } c; c.h = h; return c.u;
}
static __device__ __forceinline__ void ldsm4(uint32_t &r0, uint32_t &r1, uint32_t &r2, uint32_t &r3, uint32_t a){
  asm volatile("ldmatrix.sync.aligned.m8n8.x4.shared.b16 {%0,%1,%2,%3}, [%4];"
    : "=r"(r0), "=r"(r1), "=r"(r2), "=r"(r3) : "r"(a));
}
static __device__ __forceinline__ void mma16816(float* c, uint32_t a0, uint32_t a1, uint32_t a2, uint32_t a3,
                                                uint32_t b0, uint32_t b1){
  asm volatile("mma.sync.aligned.m16n8k16.row.col.f32.f16.f16.f32 "
    "{%0,%1,%2,%3}, {%4,%5,%6,%7}, {%8,%9}, {%0,%1,%2,%3};"
    : "+f"(c[0]), "+f"(c[1]), "+f"(c[2]), "+f"(c[3])
    : "r"(a0), "r"(a1), "r"(a2), "r"(a3), "r"(b0), "r"(b1));
}

// ---------------- fused prep ----------------
__global__ void __launch_bounds__(512) k_prep(const int* __restrict__ bidx,
                                              const float* __restrict__ embs,
                                              const float* __restrict__ W1,
                                              const float* __restrict__ b1){
  int b = blockIdx.x, t = threadIdx.x;
  if (b < BB){
    __shared__ int sb[NN];          // cached bidx for this batch (read global once)
    __shared__ int h[BB];
    __shared__ int wsum[8];
    if (t < BB) h[t] = 0;
    if (t < DD) g_acc[b*DD + t] = 0.f;
    for (int i = t; i < NN-1; i += 512) sb[i] = bidx[b*NN + 1 + i];
    __syncthreads();
    for (int i = t; i < NN-1; i += 512)
      atomicAdd(&h[sb[i]], 1);
    __syncthreads();
    int lane = t & 31, wrp = t >> 5;
    int v = 0, x = 0;
    if (t < BB){ v = h[t]; g_histT[t*BB + b] = v; }
    x = v;
    #pragma unroll
    for (int o = 1; o < 32; o <<= 1){
      int y = __shfl_up_sync(0xffffffffu, x, o);
      if (lane >= o) x += y;
    }
    if (t < BB && lane == 31) wsum[wrp] = x;
    __syncthreads();
    if (t < 32){
      int s = (t < 8) ? wsum[t] : 0;
      #pragma unroll
      for (int o = 1; o < 8; o <<= 1){
        int y = __shfl_up_sync(0xffffffffu, s, o);
        if (t >= o) s += y;
      }
      if (t < 8) wsum[t] = s;
    }
    __syncthreads();
    if (t < BB){
      int off = (wrp > 0) ? wsum[wrp-1] : 0;
      h[t] = off + x - v;
    }
    __syncthreads();
    for (int i = t; i < NN-1; i += 512){
      int s = sb[i];
      int pos = atomicAdd(&h[s], 1);
      g_perm[b*RPB + pos] = ((1 + i) << 8) | s;
    }
    if (t == 0) g_perm[b*RPB + NN-1] = (int)(0x80000000u | (1u << 8));
  } else {
    int bb = b - BB;
    __shared__ float tg[DD];
    if (t < DD) tg[t] = embs[(size_t)bb*NN*DD + t];
    __syncthreads();
    int d = t >> 2, kq = t & 3;
    const float* w = W1 + (size_t)d*2*DD + kq*32;
    const float* tgp = tg + kq*32;
    float s = 0.f;
    #pragma unroll
    for (int k = 0; k < 32; k++) s += w[k]*tgp[k];
    s += __shfl_xor_sync(0xffffffffu, s, 1);
    s += __shfl_xor_sync(0xffffffffu, s, 2);
    if (kq == 0) g_T[bb*DD + d] = s + b1[d];
  }
}

// ---------------- main: warp-autonomous 16-row slices, E/D overlay ----------------
__global__ void __launch_bounds__(256, 2) k_main(const float* __restrict__ embs,
                                                 const float* __restrict__ W1){
  extern __shared__ char sm[];
  uint32_t sbase = smem_u32(sm);
  const uint32_t Wb = sbase;

  int tid = threadIdx.x;
  int lane = tid & 31, w = tid >> 5;

  const uint32_t Eb = sbase + 32768 + (uint32_t)w*4224;   // E and D share this buffer
  float* Dw = (float*)(sm + 32768 + w*4224);

  // ---- W1b -> smem fp16 once ----
  {
    int d = tid >> 1, hh = tid & 1;
    const float4* wr = (const float4*)(W1 + (size_t)d*2*DD + DD + hh*64);
    uint32_t sw = (uint32_t)(d & 7) << 4;
    char* dst = sm + d*256;
    #pragma unroll
    for (int i = 0; i < 8; i++){
      float4 v0 = wr[2*i], v1 = wr[2*i+1];
      uint4 q;
      q.x = h2u(__floats2half2_rn(v0.x, v0.y));
      q.y = h2u(__floats2half2_rn(v0.z, v0.w));
      q.z = h2u(__floats2half2_rn(v1.x, v1.y));
      q.w = h2u(__floats2half2_rn(v1.z, v1.w));
      *(uint4*)(dst + (((uint32_t)(hh*128 + i*16)) ^ sw)) = q;
    }
  }
  __syncthreads();   // only block barrier

  const uint32_t ln15 = lane & 15;
  const uint32_t sxor = (uint32_t)(lane & 7) << 4;
  const uint32_t kbl  = (uint32_t)(lane >> 4) << 4;
  const uint32_t baseA = Eb + ln15*256;
  const uint32_t baseB = Wb + ln15*256;

  // gather mapping: lane -> (row r2 = lane>>1, half eh = lane&1)
  const int r2 = lane >> 1, eh = lane & 1;
  char* edst = (char*)sm + 32768 + w*4224 + r2*256;
  const uint32_t esw = (uint32_t)(r2 & 7) << 4;

  for (int slice = blockIdx.x*8 + w; slice < SLICES; slice += WSTRIDE){
    int batch = slice >> 7;
    int rowbase = batch*RPB + (slice & 127)*16;

    // ---- gather 16 rows -> fp16 swizzled E ----
    int pv = g_perm[rowbase + r2];
    {
      int node = (pv >> 8) & 2047;
      const float4* src = (const float4*)(embs + ((size_t)batch*NN + node)*DD + eh*64);
      #pragma unroll
      for (int half = 0; half < 2; half++){
        float4 vv[8];
        #pragma unroll
        for (int i = 0; i < 8; i++) vv[i] = src[half*8 + i];
        #pragma unroll
        for (int i = 0; i < 4; i++){
          uint4 q;
          q.x = h2u(__floats2half2_rn(vv[2*i].x, vv[2*i].y));
          q.y = h2u(__floats2half2_rn(vv[2*i].z, vv[2*i].w));
          q.z = h2u(__floats2half2_rn(vv[2*i+1].x, vv[2*i+1].y));
          q.w = h2u(__floats2half2_rn(vv[2*i+1].z, vv[2*i+1].w));
          *(uint4*)(edst + (((uint32_t)(eh*128 + half*64 + i*16)) ^ esw)) = q;
        }
      }
    }
    __syncwarp();

    // ---- MMA: 16 rows x 128 cols, K=128 ----
    float acc[16][4];
    #pragma unroll
    for (int i = 0; i < 16; i++){ acc[i][0]=0.f; acc[i][1]=0.f; acc[i][2]=0.f; acc[i][3]=0.f; }
    #pragma unroll
    for (int k0 = 0; k0 < 8; k0++){
      uint32_t ko = (((uint32_t)k0 << 5) | kbl) ^ sxor;
      uint32_t a0, a1, a2, a3;
      ldsm4(a0, a1, a2, a3, baseA + ko);
      uint32_t bad = baseB + ko;
      #pragma unroll
      for (int j = 0; j < 8; j++){
        uint32_t b0, b1, b2, b3;
        ldsm4(b0, b1, b2, b3, bad);
        bad += 16*256;
        mma16816(acc[2*j],   a0, a1, a2, a3, b0, b2);
        mma16816(acc[2*j+1], a0, a1, a2, a3, b1, b3);
      }
    }
    __syncwarp();   // all E consumed; D may overwrite buffer

    // ---- epilogue: two 8-row passes through warp-private D (overlaid on E) ----
    float tv[4];
    #pragma unroll
    for (int j = 0; j < 4; j++) tv[j] = g_T[batch*DD + lane + 32*j];

    int r0 = lane >> 2;
    int c0 = 2*(lane & 3);
    int cur = -1;
    float run[4] = {0.f, 0.f, 0.f, 0.f};

    #pragma unroll
    for (int nt = 0; nt < 16; nt++)
      *(float2*)(Dw + r0*132 + c0 + nt*8) = make_float2(acc[nt][0], acc[nt][1]);
    __syncwarp();
    #pragma unroll
    for (int r = 0; r < 8; r++){
      int pvr = __shfl_sync(0xffffffffu, pv, 2*r);
      int s = (pvr < 0) ? -1 : (pvr & 255);
      if (s != cur){
        if (cur >= 0){
          #pragma unroll
          for (int j = 0; j < 4; j++) atomicAdd(&g_acc[cur*DD + lane + 32*j], run[j]);
        }
        run[0]=run[1]=run[2]=run[3]=0.f;
        cur = s;
      }
      if (s >= 0){
        #pragma unroll
        for (int j = 0; j < 4; j++)
          run[j] += fmaxf(Dw[r*132 + lane + 32*j] + tv[j], 0.f);
      }
    }
    __syncwarp();

    #pragma unroll
    for (int nt = 0; nt < 16; nt++)
      *(float2*)(Dw + r0*132 + c0 + nt*8) = make_float2(acc[nt][2], acc[nt][3]);
    __syncwarp();
    #pragma unroll
    for (int r = 0; r < 8; r++){
      int pvr = __shfl_sync(0xffffffffu, pv, 2*(r + 8));
      int s = (pvr < 0) ? -1 : (pvr & 255);
      if (s != cur){
        if (cur >= 0){
          #pragma unroll
          for (int j = 0; j < 4; j++) atomicAdd(&g_acc[cur*DD + lane + 32*j], run[j]);
        }
        run[0]=run[1]=run[2]=run[3]=0.f;
        cur = s;
      }
      if (s >= 0){
        #pragma unroll
        for (int j = 0; j < 4; j++)
          run[j] += fmaxf(Dw[r*132 + lane + 32*j] + tv[j], 0.f);
      }
    }
    if (cur >= 0){
      #pragma unroll
      for (int j = 0; j < 4; j++) atomicAdd(&g_acc[cur*DD + lane + 32*j], run[j]);
    }
    __syncwarp();   // D reads done before next slice's E write
  }
}

// ---------------- final: out[s] = W2 . acc[s] + b2 * count_s ----------------
__global__ void __launch_bounds__(256) k_final(const float* __restrict__ W2,
                                               const float* __restrict__ b2,
                                               float* __restrict__ out){
  __shared__ float arow[DD];
  __shared__ int wsum[8];
  int s = blockIdx.x, t = threadIdx.x;
  int lane = t & 31, wrp = t >> 5;

  if (t < DD) arow[t] = g_acc[s*DD + t];
  // counts: coalesced read + warp reduce
  int c = g_histT[s*BB + t];
  #pragma unroll
  for (int o = 16; o > 0; o >>= 1) c += __shfl_xor_sync(0xffffffffu, c, o);
  if (lane == 0) wsum[wrp] = c;
  __syncthreads();
  int cnt = wsum[0] + wsum[1] + wsum[2] + wsum[3] + wsum[4] + wsum[5] + wsum[6] + wsum[7];

  int d = t >> 1, half = t & 1;
  const float* ww = W2 + (size_t)d*DD + half*64;
  const float* ar = arow + half*64;
  float r = 0.f;
  #pragma unroll
  for (int j = 0; j < 64; j++) r += ww[j]*ar[j];
  r += __shfl_xor_sync(0xffffffffu, r, 1);
  if (half == 0) out[s*DD + d] = r + b2[d]*(float)cnt;
}

// ---------------- launch ----------------
extern "C" void kernel_launch(void* const* d_in, const int* in_sizes, int n_in,
                              void* d_out, int out_size){
  const float* embs = (const float*)d_in[0];
  const float* W1   = (const float*)d_in[1];
  const float* b1   = (const float*)d_in[2];
  const float* W2   = (const float*)d_in[3];
  const float* b2   = (const float*)d_in[4];
  const int*   bidx = (const int*)d_in[5];
  float* out = (float*)d_out;

  cudaFuncSetAttribute(k_main, cudaFuncAttributeMaxDynamicSharedMemorySize, SMEM_MAIN);

  k_prep <<<2*BB, 512>>>(bidx, embs, W1, b1);
  k_main <<<GRID_MAIN, 256, SMEM_MAIN>>>(embs, W1);
  k_final<<<BB, 256>>>(W2, b2, out);
}